// round 14
// baseline (speedup 1.0000x reference)
#include <cuda_runtime.h>
#include <cuda_fp16.h>
#include <math.h>
#include <stdint.h>

#define T_   2048
#define H_   16
#define HD_  64
#define C_   1024
#define B_   2
#define M_   (B_ * T_)          // 4096

// ===================== device scratch (fp16, all single) =====================
__device__ __half g_xh[(size_t)M_ * C_];
__device__ __half g_wqh[(size_t)3 * C_ * C_];
__device__ __half g_wph[(size_t)C_ * C_];
__device__ __half g_qkvh[(size_t)M_ * 3 * C_];
__device__ __half g_atth[(size_t)M_ * C_];

// ===================== helpers =====================
__device__ __forceinline__ uint32_t smem_u32(const void* p) {
    uint32_t a;
    asm("{ .reg .u64 t; cvta.to.shared.u64 t, %1; cvt.u32.u64 %0, t; }" : "=r"(a) : "l"(p));
    return a;
}
__device__ __forceinline__ void cp_async16(uint32_t saddr, const void* gaddr) {
    asm volatile("cp.async.cg.shared.global [%0], [%1], 16;" :: "r"(saddr), "l"(gaddr));
}
#define CP_COMMIT() asm volatile("cp.async.commit_group;" ::: "memory")
#define CP_WAIT(n)  asm volatile("cp.async.wait_group %0;" :: "n"(n) : "memory")

__device__ __forceinline__ void ldsm4(uint32_t* r, uint32_t a) {
    asm volatile("ldmatrix.sync.aligned.m8n8.x4.shared.b16 {%0,%1,%2,%3}, [%4];"
                 : "=r"(r[0]), "=r"(r[1]), "=r"(r[2]), "=r"(r[3]) : "r"(a));
}
__device__ __forceinline__ void ldsm4t(uint32_t* r, uint32_t a) {
    asm volatile("ldmatrix.sync.aligned.m8n8.x4.trans.shared.b16 {%0,%1,%2,%3}, [%4];"
                 : "=r"(r[0]), "=r"(r[1]), "=r"(r[2]), "=r"(r[3]) : "r"(a));
}
__device__ __forceinline__ void mma_f16(float* d, const uint32_t* a, uint32_t b0, uint32_t b1) {
    asm volatile("mma.sync.aligned.m16n8k16.row.col.f32.f16.f16.f32 "
                 "{%0,%1,%2,%3}, {%4,%5,%6,%7}, {%8,%9}, {%0,%1,%2,%3};"
                 : "+f"(d[0]), "+f"(d[1]), "+f"(d[2]), "+f"(d[3])
                 : "r"(a[0]), "r"(a[1]), "r"(a[2]), "r"(a[3]), "r"(b0), "r"(b1));
}
__device__ __forceinline__ uint32_t packh(float hi, float lo) {
    uint32_t r;
    asm("cvt.rn.f16x2.f32 %0, %1, %2;" : "=r"(r) : "f"(hi), "f"(lo));
    return r;
}
__device__ __forceinline__ uint32_t ex2h2(uint32_t x) {
    uint32_t y; asm("ex2.approx.f16x2 %0, %1;" : "=r"(y) : "r"(x)); return y;
}
__device__ __forceinline__ float ex2(float x) {
    float y; asm("ex2.approx.ftz.f32 %0, %1;" : "=f"(y) : "f"(x)); return y;
}

// ===================== fused split fp32 -> fp16 (all single) =====================
#define N4_X   (M_ * C_ / 4)
#define N4_WQ  (3 * C_ * C_ / 4)
#define N4_WP  (C_ * C_ / 4)

__global__ void split_all(const float4* __restrict__ x, const float4* __restrict__ wq,
                          const float4* __restrict__ wp,
                          uint2* __restrict__ xh, uint2* __restrict__ wqh,
                          uint2* __restrict__ wph) {
    int i = blockIdx.x * blockDim.x + threadIdx.x;
    const float4* src;
    uint2* dst;
    int j;
    if (i < N4_X)                     { src = x;  dst = xh;  j = i; }
    else if (i < N4_X + N4_WQ)        { src = wq; dst = wqh; j = i - N4_X; }
    else if (i < N4_X + N4_WQ + N4_WP){ src = wp; dst = wph; j = i - N4_X - N4_WQ; }
    else return;
    float4 v = src[j];
    dst[j] = make_uint2(packh(v.y, v.x), packh(v.w, v.z));
}

// ===================== fp16 GEMM: C = A(MxK) @ B(NxK)^T (R12 form) ==============
#define GSTR   80
#define GTILE  (128 * GSTR)
#define GSTAGE (2 * GTILE)
#define EPI_H_STR  272
#define EPI_F_STR  528
#define GEMM_SMEM  81920

template<bool HALF_OUT>
__global__ __launch_bounds__(256, 2) void gemm_f16(
    const __half* __restrict__ Ah, const __half* __restrict__ Bh,
    float* __restrict__ Cf, __half* __restrict__ Ch,
    int M, int N, int K) {
    extern __shared__ char smc[];
    const uint32_t sb = smem_u32(smc);
    const int tid = threadIdx.x;
    const int wid = tid >> 5, lane = tid & 31;
    const int g = lane >> 2, t4 = lane & 3;
    const int i8 = lane & 7, mq = lane >> 3;
    const int wm = wid >> 1, wn = wid & 1;
    const int m0 = blockIdx.y * 128, n0 = blockIdx.x * 128;

    auto load_stage = [&](int s, int kt) {
        uint32_t base = sb + s * GSTAGE;
        #pragma unroll
        for (int it = 0; it < 4; it++) {
            int task = it * 256 + tid;
            int mat = task >> 9;
            int rem = task & 511;
            int row = rem >> 2, ch = rem & 3;
            const __half* gp = (mat == 0) ? Ah : Bh;
            int grow = ((mat == 0) ? m0 : n0) + row;
            cp_async16(base + mat * GTILE + row * GSTR + ch * 16,
                       gp + (size_t)grow * K + kt * 32 + ch * 8);
        }
    };

    float acc[2][8][4];
    #pragma unroll
    for (int mt = 0; mt < 2; mt++)
        #pragma unroll
        for (int nt = 0; nt < 8; nt++)
            #pragma unroll
            for (int i = 0; i < 4; i++) acc[mt][nt][i] = 0.f;

    const int nk = K / 32;
    load_stage(0, 0); CP_COMMIT();
    load_stage(1, 1); CP_COMMIT();
    load_stage(2, 2); CP_COMMIT();

    const uint32_t aoff = (uint32_t)((wm * 32 + (mq & 1) * 8 + i8) * GSTR + (mq >> 1) * 16);
    const uint32_t boff = (uint32_t)((wn * 64 + (mq >> 1) * 8 + i8) * GSTR + (mq & 1) * 16);

    int s = 0, ls = 3;
    for (int kb = 0; kb < nk; kb++) {
        CP_WAIT(2);
        __syncthreads();

        uint32_t sA = sb + s * GSTAGE;
        uint32_t sB = sA + GTILE;

        #pragma unroll
        for (int kc = 0; kc < 2; kc++) {
            uint32_t a[2][4];
            #pragma unroll
            for (int mt = 0; mt < 2; mt++)
                ldsm4(a[mt], sA + aoff + mt * 16 * GSTR + kc * 32);
            #pragma unroll
            for (int p = 0; p < 4; p++) {
                uint32_t b4[4];
                ldsm4(b4, sB + boff + p * 16 * GSTR + kc * 32);
                mma_f16(acc[0][2 * p],     a[0], b4[0], b4[1]);
                mma_f16(acc[1][2 * p],     a[1], b4[0], b4[1]);
                mma_f16(acc[0][2 * p + 1], a[0], b4[2], b4[3]);
                mma_f16(acc[1][2 * p + 1], a[1], b4[2], b4[3]);
            }
        }

        if (kb + 3 < nk) load_stage(ls, kb + 3);
        CP_COMMIT();
        s  = (s  + 1) & 3;
        ls = (ls + 1) & 3;
    }

    CP_WAIT(0);
    __syncthreads();

    if (HALF_OUT) {
        #pragma unroll
        for (int mt = 0; mt < 2; mt++) {
            const int r = wm * 32 + mt * 16 + g;
            #pragma unroll
            for (int nt = 0; nt < 8; nt++) {
                const int c = wn * 64 + nt * 8 + 2 * t4;
                *(uint32_t*)(smc + r * EPI_H_STR + c * 2) =
                    packh(acc[mt][nt][1], acc[mt][nt][0]);
                *(uint32_t*)(smc + (r + 8) * EPI_H_STR + c * 2) =
                    packh(acc[mt][nt][3], acc[mt][nt][2]);
            }
        }
        __syncthreads();
        #pragma unroll
        for (int it = 0; it < 8; it++) {
            int task = it * 256 + tid;
            int row = task >> 4, ch = task & 15;
            uint4 v = *(const uint4*)(smc + row * EPI_H_STR + ch * 16);
            *(uint4*)(Ch + (size_t)(m0 + row) * N + n0 + ch * 8) = v;
        }
    } else {
        #pragma unroll
        for (int mt = 0; mt < 2; mt++) {
            const int r = wm * 32 + mt * 16 + g;
            #pragma unroll
            for (int nt = 0; nt < 8; nt++) {
                const int c = wn * 64 + nt * 8 + 2 * t4;
                *(float2*)(smc + r * EPI_F_STR + c * 4) =
                    make_float2(acc[mt][nt][0], acc[mt][nt][1]);
                *(float2*)(smc + (r + 8) * EPI_F_STR + c * 4) =
                    make_float2(acc[mt][nt][2], acc[mt][nt][3]);
            }
        }
        __syncthreads();
        #pragma unroll
        for (int it = 0; it < 16; it++) {
            int task = it * 256 + tid;
            int row = task >> 5, ch = task & 31;
            uint4 v = *(const uint4*)(smc + row * EPI_F_STR + ch * 16);
            *(uint4*)(Cf + (size_t)(m0 + row) * N + n0 + ch * 4) = v;
        }
    }
}

// ===================== flash attention: R12 + warp-level masked-tile skip =========
#define ATILE   (64 * 128)              // 8192
#define AQ      (128 * 128)             // 16384
#define ASTAGE  (2 * ATILE)             // 16384 (K, V)
#define ATT_SMEM (AQ + 4 * ASTAGE)      // 81920 -> 2 CTA/SM
#define AEPI_STR 144
#define ONES2   0x3C003C00u             // (1.0h, 1.0h)

__global__ __launch_bounds__(256, 2) void attn_mma(
    const __half* __restrict__ qkvh, __half* __restrict__ oh) {
    extern __shared__ char smc[];
    const uint32_t sb = smem_u32(smc);
    const int tid = threadIdx.x;
    const int w = tid >> 5, lane = tid & 31;
    const int g = lane >> 2, t4 = lane & 3;
    const int i8 = lane & 7, mq = lane >> 3;
    const int qblk = (int)gridDim.x - 1 - (int)blockIdx.x;   // heavy CTAs first
    const int h = blockIdx.y, b = blockIdx.z;
    const int nkt = 2 * qblk + 2;
    const float CS = 0.18033688011112042f;                   // 0.125 * log2(e)
    const float NEGINF = -INFINITY;

    auto load_q = [&]() {
        #pragma unroll
        for (int it = 0; it < 4; it++) {
            int task = it * 256 + tid;
            int row = task >> 3, ch = task & 7;
            cp_async16(sb + row * 128 + ((ch ^ (row & 7)) * 16),
                       qkvh + ((size_t)(b * T_ + qblk * 128 + row)) * (3 * C_) + h * HD_ + ch * 8);
        }
    };
    auto load_kv = [&](int s, int kt) {
        #pragma unroll
        for (int it = 0; it < 4; it++) {
            int task = it * 256 + tid;
            int mat = task >> 9;             // 0 K, 1 V
            int rem = task & 511;
            int row = rem >> 3, ch = rem & 7;
            int colbase = ((mat == 0) ? C_ : 2 * C_) + h * HD_;
            cp_async16(sb + AQ + s * ASTAGE + mat * ATILE + row * 128 + ((ch ^ (row & 7)) * 16),
                       qkvh + ((size_t)(b * T_ + kt * 64 + row)) * (3 * C_) + colbase + ch * 8);
        }
    };

    load_q(); load_kv(0, 0); CP_COMMIT();
    load_kv(1, 1); CP_COMMIT();
    if (nkt > 2) load_kv(2, 2);
    CP_COMMIT();
    CP_WAIT(2);
    __syncthreads();

    uint32_t qh[4][4];
    {
        const uint32_t qrow = (uint32_t)((w * 16 + (mq & 1) * 8 + i8) * 128);
        #pragma unroll
        for (int kc = 0; kc < 4; kc++)
            ldsm4(qh[kc], sb + qrow + ((((mq >> 1) + 2 * kc) ^ i8) * 16));
    }

    float O[8][4];
    #pragma unroll
    for (int nt = 0; nt < 8; nt++)
        #pragma unroll
        for (int i = 0; i < 4; i++) O[nt][i] = 0.f;
    float lacc[4] = {0.f, 0.f, 0.f, 0.f};     // row sums via P @ ones
    float mcs0 = NEGINF, mcs1 = NEGINF;
    const int qrow0 = qblk * 128 + w * 16 + g;
    const int qrow1 = qrow0 + 8;
    const int wrow_max = qblk * 128 + w * 16 + 15;   // warp's last q-row

    const uint32_t krow = (uint32_t)(((mq >> 1) * 8 + i8) * 128);
    const uint32_t vrow = (uint32_t)(((mq & 1) * 8 + i8) * 128);

    int st = 0, ls = 3;
    for (int kb = 0; kb < nkt; kb++) {
        if (kb > 0) {
            CP_WAIT(2);
            __syncthreads();
        }
        const int kbase = kb * 64;

        if (kbase <= wrow_max) {   // fully-masked tiles contribute P==0: skip
            uint32_t sKH = sb + AQ + st * ASTAGE;
            uint32_t sVH = sKH + ATILE;

            // ---- S = Q K^T ----
            float S[8][4];
            #pragma unroll
            for (int nt = 0; nt < 8; nt++)
                #pragma unroll
                for (int i = 0; i < 4; i++) S[nt][i] = 0.f;

            #pragma unroll
            for (int kc = 0; kc < 4; kc++) {
                const uint32_t kcol = (uint32_t)((((mq & 1) + 2 * kc) ^ i8) * 16);
                #pragma unroll
                for (int p = 0; p < 4; p++) {
                    uint32_t kh4[4];
                    ldsm4(kh4, sKH + krow + p * 16 * 128 + kcol);
                    mma_f16(S[2 * p],     qh[kc], kh4[0], kh4[1]);
                    mma_f16(S[2 * p + 1], qh[kc], kh4[2], kh4[3]);
                }
            }

            // ---- causal mask ----
            if (kbase + 63 > qrow0) {
                #pragma unroll
                for (int nt = 0; nt < 8; nt++) {
                    int kc0 = kbase + nt * 8 + 2 * t4;
                    if (kc0 > qrow0)     S[nt][0] = NEGINF;
                    if (kc0 + 1 > qrow0) S[nt][1] = NEGINF;
                    if (kc0 > qrow1)     S[nt][2] = NEGINF;
                    if (kc0 + 1 > qrow1) S[nt][3] = NEGINF;
                }
            }

            // ---- online softmax: max, rescale ----
            float mx0 = NEGINF, mx1 = NEGINF;
            #pragma unroll
            for (int nt = 0; nt < 8; nt++) {
                mx0 = fmaxf(mx0, fmaxf(S[nt][0], S[nt][1]));
                mx1 = fmaxf(mx1, fmaxf(S[nt][2], S[nt][3]));
            }
            mx0 = fmaxf(mx0, __shfl_xor_sync(0xffffffffu, mx0, 1));
            mx0 = fmaxf(mx0, __shfl_xor_sync(0xffffffffu, mx0, 2));
            mx1 = fmaxf(mx1, __shfl_xor_sync(0xffffffffu, mx1, 1));
            mx1 = fmaxf(mx1, __shfl_xor_sync(0xffffffffu, mx1, 2));
            float mn0 = fmaxf(mcs0, mx0 * CS);
            float mn1 = fmaxf(mcs1, mx1 * CS);
            float a0 = ex2(mcs0 - mn0);
            float a1 = ex2(mcs1 - mn1);
            mcs0 = mn0; mcs1 = mn1;

            #pragma unroll
            for (int nt = 0; nt < 8; nt++) {
                O[nt][0] *= a0; O[nt][1] *= a0;
                O[nt][2] *= a1; O[nt][3] *= a1;
            }
            lacc[0] *= a0; lacc[1] *= a0;
            lacc[2] *= a1; lacc[3] *= a1;

            // ---- P = 2^(S*CS - mn) in f16x2 (A-frag layout), row-sums via P @ ones ----
            uint32_t ph[4][4];
            #pragma unroll
            for (int j = 0; j < 4; j++) {
                ph[j][0] = ex2h2(packh(fmaf(S[2 * j][1],     CS, -mn0), fmaf(S[2 * j][0],     CS, -mn0)));
                ph[j][1] = ex2h2(packh(fmaf(S[2 * j][3],     CS, -mn1), fmaf(S[2 * j][2],     CS, -mn1)));
                ph[j][2] = ex2h2(packh(fmaf(S[2 * j + 1][1], CS, -mn0), fmaf(S[2 * j + 1][0], CS, -mn0)));
                ph[j][3] = ex2h2(packh(fmaf(S[2 * j + 1][3], CS, -mn1), fmaf(S[2 * j + 1][2], CS, -mn1)));
                mma_f16(lacc, ph[j], ONES2, ONES2);
            }

            // ---- O += P V ----
            #pragma unroll
            for (int j = 0; j < 4; j++) {
                #pragma unroll
                for (int p = 0; p < 4; p++) {
                    const uint32_t vcol = (uint32_t)((((mq >> 1) + 2 * p) ^ i8) * 16);
                    uint32_t vh4[4];
                    ldsm4t(vh4, sVH + vrow + j * 16 * 128 + vcol);
                    mma_f16(O[2 * p],     ph[j], vh4[0], vh4[1]);
                    mma_f16(O[2 * p + 1], ph[j], vh4[2], vh4[3]);
                }
            }
        }

        if (kb + 3 < nkt) load_kv(ls, kb + 3);
        CP_COMMIT();
        st = (st + 1) & 3;
        ls = (ls + 1) & 3;
    }

    // ---- staged epilogue ----
    const float rl0 = 1.0f / lacc[0], rl1 = 1.0f / lacc[2];
    __syncthreads();
    {
        const int r = w * 16 + g;
        #pragma unroll
        for (int nt = 0; nt < 8; nt++) {
            const int c = nt * 8 + 2 * t4;
            *(uint32_t*)(smc + r * AEPI_STR + c * 2) =
                packh(O[nt][1] * rl0, O[nt][0] * rl0);
            *(uint32_t*)(smc + (r + 8) * AEPI_STR + c * 2) =
                packh(O[nt][3] * rl1, O[nt][2] * rl1);
        }
    }
    __syncthreads();
    #pragma unroll
    for (int it = 0; it < 4; it++) {
        int task = it * 256 + tid;
        int row = task >> 3, ch = task & 7;
        uint4 v = *(const uint4*)(smc + row * AEPI_STR + ch * 16);
        *(uint4*)(oh + ((size_t)(b * T_ + qblk * 128 + row)) * C_ + h * HD_ + ch * 8) = v;
    }
}

// ===================== launch =====================
extern "C" void kernel_launch(void* const* d_in, const int* in_sizes, int n_in,
                              void* d_out, int out_size) {
    (void)in_sizes; (void)n_in; (void)out_size;
    const float* x      = (const float*)d_in[0];
    const float* w_qkv  = (const float*)d_in[1];
    const float* w_proj = (const float*)d_in[2];
    float* out = (float*)d_out;

    __half *xh, *wqh, *wph, *qkvh, *atth;
    cudaGetSymbolAddress((void**)&xh, g_xh);
    cudaGetSymbolAddress((void**)&wqh, g_wqh);
    cudaGetSymbolAddress((void**)&wph, g_wph);
    cudaGetSymbolAddress((void**)&qkvh, g_qkvh);
    cudaGetSymbolAddress((void**)&atth, g_atth);

    cudaFuncSetAttribute((const void*)gemm_f16<true>,
                         cudaFuncAttributeMaxDynamicSharedMemorySize, GEMM_SMEM);
    cudaFuncSetAttribute((const void*)gemm_f16<false>,
                         cudaFuncAttributeMaxDynamicSharedMemorySize, GEMM_SMEM);
    cudaFuncSetAttribute((const void*)attn_mma,
                         cudaFuncAttributeMaxDynamicSharedMemorySize, ATT_SMEM);

    // 0) fused input split (all single fp16)
    {
        int total = N4_X + N4_WQ + N4_WP;
        split_all<<<(total + 255) / 256, 256>>>(
            (const float4*)x, (const float4*)w_qkv, (const float4*)w_proj,
            (uint2*)xh, (uint2*)wqh, (uint2*)wph);
    }

    // 1) qkv = x @ w_qkv^T  -> fp16
    gemm_f16<true><<<dim3(3 * C_ / 128, M_ / 128), 256, GEMM_SMEM>>>(
        xh, wqh, nullptr, qkvh, M_, 3 * C_, C_);

    // 2) attention -> fp16  (Br=128)
    attn_mma<<<dim3(T_ / 128, H_, B_), 256, ATT_SMEM>>>(qkvh, atth);

    // 3) out = att @ w_proj^T  -> fp32
    gemm_f16<false><<<dim3(C_ / 128, M_ / 128), 256, GEMM_SMEM>>>(
        atth, wph, out, nullptr, M_, C_, C_);
}

// round 16
// speedup vs baseline: 1.1172x; 1.1172x over previous
#include <cuda_runtime.h>
#include <cuda_fp16.h>
#include <math.h>
#include <stdint.h>

#define T_   2048
#define H_   16
#define HD_  64
#define C_   1024
#define B_   2
#define M_   (B_ * T_)          // 4096

// ===================== device scratch (fp16, all single) =====================
__device__ __half g_xh[(size_t)M_ * C_];
__device__ __half g_wqh[(size_t)3 * C_ * C_];
__device__ __half g_wph[(size_t)C_ * C_];
__device__ __half g_qkvh[(size_t)M_ * 3 * C_];
__device__ __half g_atth[(size_t)M_ * C_];

// ===================== helpers =====================
__device__ __forceinline__ uint32_t smem_u32(const void* p) {
    uint32_t a;
    asm("{ .reg .u64 t; cvta.to.shared.u64 t, %1; cvt.u32.u64 %0, t; }" : "=r"(a) : "l"(p));
    return a;
}
__device__ __forceinline__ void cp_async16(uint32_t saddr, const void* gaddr) {
    asm volatile("cp.async.cg.shared.global [%0], [%1], 16;" :: "r"(saddr), "l"(gaddr));
}
#define CP_COMMIT() asm volatile("cp.async.commit_group;" ::: "memory")
#define CP_WAIT(n)  asm volatile("cp.async.wait_group %0;" :: "n"(n) : "memory")

__device__ __forceinline__ void ldsm4(uint32_t* r, uint32_t a) {
    asm volatile("ldmatrix.sync.aligned.m8n8.x4.shared.b16 {%0,%1,%2,%3}, [%4];"
                 : "=r"(r[0]), "=r"(r[1]), "=r"(r[2]), "=r"(r[3]) : "r"(a));
}
__device__ __forceinline__ void ldsm4t(uint32_t* r, uint32_t a) {
    asm volatile("ldmatrix.sync.aligned.m8n8.x4.trans.shared.b16 {%0,%1,%2,%3}, [%4];"
                 : "=r"(r[0]), "=r"(r[1]), "=r"(r[2]), "=r"(r[3]) : "r"(a));
}
__device__ __forceinline__ void mma_f16(float* d, const uint32_t* a, uint32_t b0, uint32_t b1) {
    asm volatile("mma.sync.aligned.m16n8k16.row.col.f32.f16.f16.f32 "
                 "{%0,%1,%2,%3}, {%4,%5,%6,%7}, {%8,%9}, {%0,%1,%2,%3};"
                 : "+f"(d[0]), "+f"(d[1]), "+f"(d[2]), "+f"(d[3])
                 : "r"(a[0]), "r"(a[1]), "r"(a[2]), "r"(a[3]), "r"(b0), "r"(b1));
}
__device__ __forceinline__ uint32_t packh(float hi, float lo) {
    uint32_t r;
    asm("cvt.rn.f16x2.f32 %0, %1, %2;" : "=r"(r) : "f"(hi), "f"(lo));
    return r;
}
__device__ __forceinline__ uint32_t ex2h2(uint32_t x) {
    uint32_t y; asm("ex2.approx.f16x2 %0, %1;" : "=r"(y) : "r"(x)); return y;
}
__device__ __forceinline__ float ex2(float x) {
    float y; asm("ex2.approx.ftz.f32 %0, %1;" : "=f"(y) : "f"(x)); return y;
}

// ===================== fused split fp32 -> fp16 (all single) =====================
#define N4_X   (M_ * C_ / 4)
#define N4_WQ  (3 * C_ * C_ / 4)
#define N4_WP  (C_ * C_ / 4)

__global__ void split_all(const float4* __restrict__ x, const float4* __restrict__ wq,
                          const float4* __restrict__ wp,
                          uint2* __restrict__ xh, uint2* __restrict__ wqh,
                          uint2* __restrict__ wph) {
    int i = blockIdx.x * blockDim.x + threadIdx.x;
    const float4* src;
    uint2* dst;
    int j;
    if (i < N4_X)                     { src = x;  dst = xh;  j = i; }
    else if (i < N4_X + N4_WQ)        { src = wq; dst = wqh; j = i - N4_X; }
    else if (i < N4_X + N4_WQ + N4_WP){ src = wp; dst = wph; j = i - N4_X - N4_WQ; }
    else return;
    float4 v = src[j];
    dst[j] = make_uint2(packh(v.y, v.x), packh(v.w, v.z));
}

// ===================== fp16 GEMM: C = A(MxK) @ B(NxK)^T ==========================
// BK=64, 128B XOR-swizzled rows (attention-proven layout), 3-stage ring,
// ONE barrier per 64 K-columns (16 total for K=1024).
#define GTILE  (128 * 128)            // 16384 B (128 rows x 128B)
#define GSTAGE (2 * GTILE)            // 32768 (A, B)
#define EPI_H_STR  272
#define EPI_F_STR  528
#define GEMM_SMEM  98304              // 3 * GSTAGE; also >= epilogue staging

template<bool HALF_OUT>
__global__ __launch_bounds__(256, 2) void gemm_f16(
    const __half* __restrict__ Ah, const __half* __restrict__ Bh,
    float* __restrict__ Cf, __half* __restrict__ Ch,
    int M, int N, int K) {
    extern __shared__ char smc[];
    const uint32_t sb = smem_u32(smc);
    const int tid = threadIdx.x;
    const int wid = tid >> 5, lane = tid & 31;
    const int g = lane >> 2, t4 = lane & 3;
    const int i8 = lane & 7, mq = lane >> 3;
    const int wm = wid >> 1, wn = wid & 1;
    const int m0 = blockIdx.y * 128, n0 = blockIdx.x * 128;

    // one stage = A tile + B tile, 128 rows x 64 fp16 (=128B), XOR swizzle
    auto load_stage = [&](int s, int kt) {
        uint32_t base = sb + s * GSTAGE;
        #pragma unroll
        for (int it = 0; it < 8; it++) {
            int task = it * 256 + tid;                 // 2048 tasks
            int mat = task >> 10;                      // 0=A, 1=B
            int rem = task & 1023;
            int row = rem >> 3, ch = rem & 7;
            const __half* gp = (mat == 0) ? Ah : Bh;
            int grow = ((mat == 0) ? m0 : n0) + row;
            cp_async16(base + mat * GTILE + row * 128 + ((ch ^ (row & 7)) * 16),
                       gp + (size_t)grow * K + kt * 64 + ch * 8);
        }
    };

    float acc[2][8][4];
    #pragma unroll
    for (int mt = 0; mt < 2; mt++)
        #pragma unroll
        for (int nt = 0; nt < 8; nt++)
            #pragma unroll
            for (int i = 0; i < 4; i++) acc[mt][nt][i] = 0.f;

    const int nk = K / 64;            // 16
    load_stage(0, 0); CP_COMMIT();
    load_stage(1, 1); CP_COMMIT();

    const uint32_t arow = (uint32_t)((wm * 32 + (mq & 1) * 8 + i8) * 128);
    const uint32_t brow = (uint32_t)((wn * 64 + (mq >> 1) * 8 + i8) * 128);

    int s = 0, ls = 2;
    for (int kb = 0; kb < nk; kb++) {
        CP_WAIT(1);
        __syncthreads();

        uint32_t sA = sb + s * GSTAGE;
        uint32_t sB = sA + GTILE;

        #pragma unroll
        for (int kc = 0; kc < 4; kc++) {
            const uint32_t acol = (uint32_t)((((mq >> 1) + 2 * kc) ^ i8) * 16);
            const uint32_t bcol = (uint32_t)((((mq & 1) + 2 * kc) ^ i8) * 16);
            uint32_t a[2][4];
            #pragma unroll
            for (int mt = 0; mt < 2; mt++)
                ldsm4(a[mt], sA + arow + mt * 16 * 128 + acol);
            #pragma unroll
            for (int p = 0; p < 4; p++) {
                uint32_t b4[4];
                ldsm4(b4, sB + brow + p * 16 * 128 + bcol);
                mma_f16(acc[0][2 * p],     a[0], b4[0], b4[1]);
                mma_f16(acc[1][2 * p],     a[1], b4[0], b4[1]);
                mma_f16(acc[0][2 * p + 1], a[0], b4[2], b4[3]);
                mma_f16(acc[1][2 * p + 1], a[1], b4[2], b4[3]);
            }
        }

        if (kb + 2 < nk) load_stage(ls, kb + 2);
        CP_COMMIT();                  // uniform group count (empty in tail)
        s  = (s  == 2) ? 0 : s + 1;
        ls = (ls == 2) ? 0 : ls + 1;
    }

    CP_WAIT(0);
    __syncthreads();

    if (HALF_OUT) {
        #pragma unroll
        for (int mt = 0; mt < 2; mt++) {
            const int r = wm * 32 + mt * 16 + g;
            #pragma unroll
            for (int nt = 0; nt < 8; nt++) {
                const int c = wn * 64 + nt * 8 + 2 * t4;
                *(uint32_t*)(smc + r * EPI_H_STR + c * 2) =
                    packh(acc[mt][nt][1], acc[mt][nt][0]);
                *(uint32_t*)(smc + (r + 8) * EPI_H_STR + c * 2) =
                    packh(acc[mt][nt][3], acc[mt][nt][2]);
            }
        }
        __syncthreads();
        #pragma unroll
        for (int it = 0; it < 8; it++) {
            int task = it * 256 + tid;
            int row = task >> 4, ch = task & 15;
            uint4 v = *(const uint4*)(smc + row * EPI_H_STR + ch * 16);
            *(uint4*)(Ch + (size_t)(m0 + row) * N + n0 + ch * 8) = v;
        }
    } else {
        #pragma unroll
        for (int mt = 0; mt < 2; mt++) {
            const int r = wm * 32 + mt * 16 + g;
            #pragma unroll
            for (int nt = 0; nt < 8; nt++) {
                const int c = wn * 64 + nt * 8 + 2 * t4;
                *(float2*)(smc + r * EPI_F_STR + c * 4) =
                    make_float2(acc[mt][nt][0], acc[mt][nt][1]);
                *(float2*)(smc + (r + 8) * EPI_F_STR + c * 4) =
                    make_float2(acc[mt][nt][2], acc[mt][nt][3]);
            }
        }
        __syncthreads();
        #pragma unroll
        for (int it = 0; it < 16; it++) {
            int task = it * 256 + tid;
            int row = task >> 5, ch = task & 31;
            uint4 v = *(const uint4*)(smc + row * EPI_F_STR + ch * 16);
            *(uint4*)(Cf + (size_t)(m0 + row) * N + n0 + ch * 4) = v;
        }
    }
}

// ===================== flash attention: exact R12 form ============================
#define ATILE   (64 * 128)              // 8192
#define AQ      (128 * 128)             // 16384
#define ASTAGE  (2 * ATILE)             // 16384 (K, V)
#define ATT_SMEM (AQ + 4 * ASTAGE)      // 81920 -> 2 CTA/SM
#define AEPI_STR 144
#define ONES2   0x3C003C00u             // (1.0h, 1.0h)

__global__ __launch_bounds__(256, 2) void attn_mma(
    const __half* __restrict__ qkvh, __half* __restrict__ oh) {
    extern __shared__ char smc[];
    const uint32_t sb = smem_u32(smc);
    const int tid = threadIdx.x;
    const int w = tid >> 5, lane = tid & 31;
    const int g = lane >> 2, t4 = lane & 3;
    const int i8 = lane & 7, mq = lane >> 3;
    const int qblk = (int)gridDim.x - 1 - (int)blockIdx.x;   // heavy CTAs first
    const int h = blockIdx.y, b = blockIdx.z;
    const int nkt = 2 * qblk + 2;
    const float CS = 0.18033688011112042f;                   // 0.125 * log2(e)
    const float NEGINF = -INFINITY;

    auto load_q = [&]() {
        #pragma unroll
        for (int it = 0; it < 4; it++) {
            int task = it * 256 + tid;
            int row = task >> 3, ch = task & 7;
            cp_async16(sb + row * 128 + ((ch ^ (row & 7)) * 16),
                       qkvh + ((size_t)(b * T_ + qblk * 128 + row)) * (3 * C_) + h * HD_ + ch * 8);
        }
    };
    auto load_kv = [&](int s, int kt) {
        #pragma unroll
        for (int it = 0; it < 4; it++) {
            int task = it * 256 + tid;
            int mat = task >> 9;             // 0 K, 1 V
            int rem = task & 511;
            int row = rem >> 3, ch = rem & 7;
            int colbase = ((mat == 0) ? C_ : 2 * C_) + h * HD_;
            cp_async16(sb + AQ + s * ASTAGE + mat * ATILE + row * 128 + ((ch ^ (row & 7)) * 16),
                       qkvh + ((size_t)(b * T_ + kt * 64 + row)) * (3 * C_) + colbase + ch * 8);
        }
    };

    load_q(); load_kv(0, 0); CP_COMMIT();
    load_kv(1, 1); CP_COMMIT();
    if (nkt > 2) load_kv(2, 2);
    CP_COMMIT();
    CP_WAIT(2);
    __syncthreads();

    uint32_t qh[4][4];
    {
        const uint32_t qrow = (uint32_t)((w * 16 + (mq & 1) * 8 + i8) * 128);
        #pragma unroll
        for (int kc = 0; kc < 4; kc++)
            ldsm4(qh[kc], sb + qrow + ((((mq >> 1) + 2 * kc) ^ i8) * 16));
    }

    float O[8][4];
    #pragma unroll
    for (int nt = 0; nt < 8; nt++)
        #pragma unroll
        for (int i = 0; i < 4; i++) O[nt][i] = 0.f;
    float lacc[4] = {0.f, 0.f, 0.f, 0.f};     // row sums via P @ ones
    float mcs0 = NEGINF, mcs1 = NEGINF;
    const int qrow0 = qblk * 128 + w * 16 + g;
    const int qrow1 = qrow0 + 8;

    const uint32_t krow = (uint32_t)(((mq >> 1) * 8 + i8) * 128);
    const uint32_t vrow = (uint32_t)(((mq & 1) * 8 + i8) * 128);

    int st = 0, ls = 3;
    for (int kb = 0; kb < nkt; kb++) {
        if (kb > 0) {
            CP_WAIT(2);
            __syncthreads();
        }
        uint32_t sKH = sb + AQ + st * ASTAGE;
        uint32_t sVH = sKH + ATILE;

        // ---- S = Q K^T ----
        float S[8][4];
        #pragma unroll
        for (int nt = 0; nt < 8; nt++)
            #pragma unroll
            for (int i = 0; i < 4; i++) S[nt][i] = 0.f;

        #pragma unroll
        for (int kc = 0; kc < 4; kc++) {
            const uint32_t kcol = (uint32_t)((((mq & 1) + 2 * kc) ^ i8) * 16);
            #pragma unroll
            for (int p = 0; p < 4; p++) {
                uint32_t kh4[4];
                ldsm4(kh4, sKH + krow + p * 16 * 128 + kcol);
                mma_f16(S[2 * p],     qh[kc], kh4[0], kh4[1]);
                mma_f16(S[2 * p + 1], qh[kc], kh4[2], kh4[3]);
            }
        }

        // ---- causal mask ----
        const int kbase = kb * 64;
        if (kbase + 63 > qrow0) {
            #pragma unroll
            for (int nt = 0; nt < 8; nt++) {
                int kc0 = kbase + nt * 8 + 2 * t4;
                if (kc0 > qrow0)     S[nt][0] = NEGINF;
                if (kc0 + 1 > qrow0) S[nt][1] = NEGINF;
                if (kc0 > qrow1)     S[nt][2] = NEGINF;
                if (kc0 + 1 > qrow1) S[nt][3] = NEGINF;
            }
        }

        // ---- online softmax: max, rescale ----
        float mx0 = NEGINF, mx1 = NEGINF;
        #pragma unroll
        for (int nt = 0; nt < 8; nt++) {
            mx0 = fmaxf(mx0, fmaxf(S[nt][0], S[nt][1]));
            mx1 = fmaxf(mx1, fmaxf(S[nt][2], S[nt][3]));
        }
        mx0 = fmaxf(mx0, __shfl_xor_sync(0xffffffffu, mx0, 1));
        mx0 = fmaxf(mx0, __shfl_xor_sync(0xffffffffu, mx0, 2));
        mx1 = fmaxf(mx1, __shfl_xor_sync(0xffffffffu, mx1, 1));
        mx1 = fmaxf(mx1, __shfl_xor_sync(0xffffffffu, mx1, 2));
        float mn0 = fmaxf(mcs0, mx0 * CS);
        float mn1 = fmaxf(mcs1, mx1 * CS);
        float a0 = ex2(mcs0 - mn0);
        float a1 = ex2(mcs1 - mn1);
        mcs0 = mn0; mcs1 = mn1;

        #pragma unroll
        for (int nt = 0; nt < 8; nt++) {
            O[nt][0] *= a0; O[nt][1] *= a0;
            O[nt][2] *= a1; O[nt][3] *= a1;
        }
        lacc[0] *= a0; lacc[1] *= a0;
        lacc[2] *= a1; lacc[3] *= a1;

        // ---- P = 2^(S*CS - mn) in f16x2 (A-frag layout), row-sums via P @ ones ----
        uint32_t ph[4][4];
        #pragma unroll
        for (int j = 0; j < 4; j++) {
            ph[j][0] = ex2h2(packh(fmaf(S[2 * j][1],     CS, -mn0), fmaf(S[2 * j][0],     CS, -mn0)));
            ph[j][1] = ex2h2(packh(fmaf(S[2 * j][3],     CS, -mn1), fmaf(S[2 * j][2],     CS, -mn1)));
            ph[j][2] = ex2h2(packh(fmaf(S[2 * j + 1][1], CS, -mn0), fmaf(S[2 * j + 1][0], CS, -mn0)));
            ph[j][3] = ex2h2(packh(fmaf(S[2 * j + 1][3], CS, -mn1), fmaf(S[2 * j + 1][2], CS, -mn1)));
            mma_f16(lacc, ph[j], ONES2, ONES2);
        }

        // ---- O += P V ----
        #pragma unroll
        for (int j = 0; j < 4; j++) {
            #pragma unroll
            for (int p = 0; p < 4; p++) {
                const uint32_t vcol = (uint32_t)((((mq >> 1) + 2 * p) ^ i8) * 16);
                uint32_t vh4[4];
                ldsm4t(vh4, sVH + vrow + j * 16 * 128 + vcol);
                mma_f16(O[2 * p],     ph[j], vh4[0], vh4[1]);
                mma_f16(O[2 * p + 1], ph[j], vh4[2], vh4[3]);
            }
        }

        if (kb + 3 < nkt) load_kv(ls, kb + 3);
        CP_COMMIT();
        st = (st + 1) & 3;
        ls = (ls + 1) & 3;
    }

    // ---- staged epilogue ----
    const float rl0 = 1.0f / lacc[0], rl1 = 1.0f / lacc[2];
    __syncthreads();
    {
        const int r = w * 16 + g;
        #pragma unroll
        for (int nt = 0; nt < 8; nt++) {
            const int c = nt * 8 + 2 * t4;
            *(uint32_t*)(smc + r * AEPI_STR + c * 2) =
                packh(O[nt][1] * rl0, O[nt][0] * rl0);
            *(uint32_t*)(smc + (r + 8) * AEPI_STR + c * 2) =
                packh(O[nt][3] * rl1, O[nt][2] * rl1);
        }
    }
    __syncthreads();
    #pragma unroll
    for (int it = 0; it < 4; it++) {
        int task = it * 256 + tid;
        int row = task >> 3, ch = task & 7;
        uint4 v = *(const uint4*)(smc + row * AEPI_STR + ch * 16);
        *(uint4*)(oh + ((size_t)(b * T_ + qblk * 128 + row)) * C_ + h * HD_ + ch * 8) = v;
    }
}

// ===================== launch =====================
extern "C" void kernel_launch(void* const* d_in, const int* in_sizes, int n_in,
                              void* d_out, int out_size) {
    (void)in_sizes; (void)n_in; (void)out_size;
    const float* x      = (const float*)d_in[0];
    const float* w_qkv  = (const float*)d_in[1];
    const float* w_proj = (const float*)d_in[2];
    float* out = (float*)d_out;

    __half *xh, *wqh, *wph, *qkvh, *atth;
    cudaGetSymbolAddress((void**)&xh, g_xh);
    cudaGetSymbolAddress((void**)&wqh, g_wqh);
    cudaGetSymbolAddress((void**)&wph, g_wph);
    cudaGetSymbolAddress((void**)&qkvh, g_qkvh);
    cudaGetSymbolAddress((void**)&atth, g_atth);

    cudaFuncSetAttribute((const void*)gemm_f16<true>,
                         cudaFuncAttributeMaxDynamicSharedMemorySize, GEMM_SMEM);
    cudaFuncSetAttribute((const void*)gemm_f16<false>,
                         cudaFuncAttributeMaxDynamicSharedMemorySize, GEMM_SMEM);
    cudaFuncSetAttribute((const void*)attn_mma,
                         cudaFuncAttributeMaxDynamicSharedMemorySize, ATT_SMEM);

    // 0) fused input split (all single fp16)
    {
        int total = N4_X + N4_WQ + N4_WP;
        split_all<<<(total + 255) / 256, 256>>>(
            (const float4*)x, (const float4*)w_qkv, (const float4*)w_proj,
            (uint2*)xh, (uint2*)wqh, (uint2*)wph);
    }

    // 1) qkv = x @ w_qkv^T  -> fp16
    gemm_f16<true><<<dim3(3 * C_ / 128, M_ / 128), 256, GEMM_SMEM>>>(
        xh, wqh, nullptr, qkvh, M_, 3 * C_, C_);

    // 2) attention -> fp16  (Br=128)
    attn_mma<<<dim3(T_ / 128, H_, B_), 256, ATT_SMEM>>>(qkvh, atth);

    // 3) out = att @ w_proj^T  -> fp32
    gemm_f16<false><<<dim3(C_ / 128, M_ / 128), 256, GEMM_SMEM>>>(
        atth, wph, out, nullptr, M_, C_, C_);
}